// round 7
// baseline (speedup 1.0000x reference)
#include <cuda_runtime.h>
#include <math.h>

#define Bc 8
#define Sc 96
#define Tc 96
#define Fc 64
#define Hc 64
#define H2 128
#define TILE 8
#define TG 12       // 96 / TILE
#define NDIAG 23    // 2*TG - 1
#define NTHREADS 512
#define H0S 68      // padded stride for depth-1 h0 staging (bank-conflict-free)

// Unmasked recurrence state (scratch): halos + depth-1 projections read this.
__device__ float g_hx[2][Bc][Sc][Tc][Hc];
__device__ float g_hy[2][Bc][Sc][Tc][Hc];
// Depth-0 input projections: px depends only on (b,i), py only on (b,j).
__device__ float g_px0[Bc][Sc][Hc];
__device__ float g_py0[Bc][Tc][Hc];

__device__ __forceinline__ float ftanh(float x) {
    float e = __expf(-2.0f * fabsf(x));
    float r = __fdividef(1.0f - e, 1.0f + e);
    return copysignf(r, x);
}

// ---------------------------------------------------------------------------
// Depth-0 projections: g_px0[b][i][:] = src[b,i,:] @ Wi_x[0];  g_py0 likewise.
// ---------------------------------------------------------------------------
__global__ void proj0_kernel(const float* __restrict__ src,
                             const float* __restrict__ trg,
                             const float* __restrict__ Wix,
                             const float* __restrict__ Wiy)
{
    __shared__ float row[Fc];
    const int r = blockIdx.x;
    const int k = threadIdx.x;
    const float* W;
    const float* inrow;
    float* outp;
    if (r < Bc * Sc) {
        inrow = src + r * Fc;  W = Wix;  outp = &g_px0[0][0][0] + r * Hc;
    } else {
        int rr = r - Bc * Sc;
        inrow = trg + rr * Fc; W = Wiy;  outp = &g_py0[0][0][0] + rr * Hc;
    }
    row[k] = inrow[k];
    __syncthreads();
    float acc = 0.f;
#pragma unroll 8
    for (int f = 0; f < Fc; f++) acc += row[f] * W[f * Hc + k];
    outp[k] = acc;
}

// ---------------------------------------------------------------------------
// Wavefront tile kernel. One CTA = one (depth, tile, batch). 512 threads =
// 64 output-pairs x 8 K-slices. Recurrence weights in registers (16 rows x 2
// cols per thread, PERMUTED by the rotation schedule); partial dots reduced
// via 3 butterfly shuffles. Rotated h-chunk reads are bank-conflict-free.
// ---------------------------------------------------------------------------
// smem layout (floats):
//   [0      : 8192 )  STW (depth-1 prologue)  /  P (overlaid after barrier)
//   [8192   : 12544)  H0X [64][68]
//   [12544  : 16896)  H0Y [64][68]
//   [16896  : 17920)  HX  [2][8][64]
//   [17920  : 18944)  HY  [2][8][64]
//   [18944  : 19456)  HXtop  [8][64]
//   [19456  : 19968)  HYleft [8][64]
#define SMEM_FLOATS 19968
#define SMEM_BYTES  (SMEM_FLOATS * 4)

__global__ void __launch_bounds__(NTHREADS, 2) wave_kernel(
    const float* __restrict__ Whx, const float* __restrict__ Why,
    const float* __restrict__ bx,  const float* __restrict__ by,
    const float* __restrict__ Wix, const float* __restrict__ Wiy,
    const int*   __restrict__ slen, const int* __restrict__ tlen,
    float* __restrict__ out, int s, int n0)
{
    extern __shared__ float smem[];
    float* STW    = smem;             // depth-1 staging, overlaid by P
    float* P      = smem;             // [64][128] cell-major proj (+bias)
    float* H0X    = smem + 8192;      // [64][H0S]
    float* H0Y    = H0X + 64 * H0S;   // [64][H0S]
    float* HX     = H0Y + 64 * H0S;   // [2][8][64] ping-pong hx along diagonal
    float* HY     = HX + 1024;        // [2][8][64]
    float* HXtop  = HY + 1024;        // [8][64] hx halo from tile above
    float* HYleft = HXtop + 512;      // [8][64] hy halo from tile left

    const int t    = threadIdx.x;
    const int slot = blockIdx.x >> 3;
    const int b    = blockIdx.x & 7;

    int depth, diag, pos;
    if (slot < n0) { depth = 0; diag = s;     pos = slot; }
    else           { depth = 1; diag = s - 1; pos = slot - n0; }
    int lo = diag - (TG - 1); if (lo < 0) lo = 0;
    const int ti = lo + pos;
    const int tj = diag - ti;
    const int i0 = ti * TILE, j0 = tj * TILE;

    const float* bxd = bx + depth * Hc;
    const float* byd = by + depth * Hc;

    // ---- halos from neighbor tiles (unmasked scratch), zeros at border ----
    {
        int rr = t >> 6, k = t & 63;
        HXtop[t]  = (ti > 0) ? g_hx[depth][b][i0 - 1][j0 + rr][k] : 0.f;
        HYleft[t] = (tj > 0) ? g_hy[depth][b][i0 + rr][j0 - 1][k] : 0.f;
    }

    // ---- register-resident recurrence weights (rotated/permuted layout) ----
    const int lane = t & 31;
    const int kq   = lane >> 2;                      // 0..7 : K-slice
    const int kh   = ((t >> 5) << 2) | (lane & 3);   // 0..63 : output pair
    const int k0   = kh * 2;
    const bool isx = (kh < 32);
    const int  kb  = isx ? k0 : (k0 - Hc);
    const int  hofs = (kq & 3) * 16;
    const int  rot  = (kq + (kq >> 2)) & 3;          // kq<4: kq ; kq>=4: kq+1 (mod 4)
    const int  co0 = ((rot    ) & 3) * 4;
    const int  co1 = ((rot + 1) & 3) * 4;
    const int  co2 = ((rot + 2) & 3) * 4;
    const int  co3 = ((rot + 3) & 3) * 4;

    float2 w[16];
    {
        const float* Wbase = isx ? (Whx + depth * H2 * Hc + k0)
                                 : (Why + depth * H2 * Hc + (k0 - Hc));
#pragma unroll
        for (int u4 = 0; u4 < 4; u4++) {
            int cou = ((rot + u4) & 3) * 4;
#pragma unroll
            for (int e = 0; e < 4; e++)
                w[u4 * 4 + e] = *(const float2*)(Wbase + (kq * 16 + cou + e) * Hc);
        }
    }

    // ---- per-cell input projections P[cell][k] with bias folded in ----
    if (depth == 0) {
        for (int idx = t; idx < 64 * H2; idx += NTHREADS) {
            int c = idx >> 7, k = idx & 127;
            int ii = c >> 3, jj = c & 7;
            P[idx] = (k < Hc) ? g_px0[b][i0 + ii][k] + bxd[k]
                              : g_py0[b][j0 + jj][k - Hc] + byd[k - Hc];
        }
        __syncthreads();
    } else {
        // stage Wi (combined) and previous-depth h tiles into smem
        for (int idx = t; idx < 64 * H2; idx += NTHREADS) {
            int f = idx >> 7, k = idx & 127;
            STW[idx] = (k < Hc) ? Wix[Fc * Hc + f * Hc + k]
                                : Wiy[Fc * Hc + f * Hc + (k - Hc)];
        }
        for (int idx = t; idx < 64 * Fc; idx += NTHREADS) {
            int c = idx >> 6, f = idx & 63;
            int ii = c >> 3, jj = c & 7;
            H0X[c * H0S + f] = g_hx[0][b][i0 + ii][j0 + jj][f];
            H0Y[c * H0S + f] = g_hy[0][b][i0 + ii][j0 + jj][f];
        }
        __syncthreads();
        // P[c][k] = h0 @ Wi + bias ; thread: cell c = t>>3, 16 k's as
        // k = (t&7)*4 + e4*32  (conflict-free float4 columns)
        {
            const int c   = t >> 3;
            const int kb4 = (t & 7) * 4;
            float4 acc[4] = {{0,0,0,0},{0,0,0,0},{0,0,0,0},{0,0,0,0}};
            const float* HrowX = H0X + c * H0S;
            const float* HrowY = H0Y + c * H0S;
#pragma unroll 4
            for (int f = 0; f < Fc; f++) {
                float hx0 = HrowX[f];
                float hy0 = HrowY[f];
                const float* wr = STW + f * H2 + kb4;
#pragma unroll
                for (int e4 = 0; e4 < 4; e4++) {
                    float4 wv = *(const float4*)(wr + e4 * 32);
                    float hv = (e4 < 2) ? hx0 : hy0;
                    acc[e4].x += hv * wv.x; acc[e4].y += hv * wv.y;
                    acc[e4].z += hv * wv.z; acc[e4].w += hv * wv.w;
                }
            }
            __syncthreads();   // everyone done reading STW before P overlays it
#pragma unroll
            for (int e4 = 0; e4 < 4; e4++) {
                int k = kb4 + e4 * 32;
                float4 bb;
                if (k < Hc) bb = *(const float4*)(bxd + k);
                else        bb = *(const float4*)(byd + (k - Hc));
                float4 v = acc[e4];
                v.x += bb.x; v.y += bb.y; v.z += bb.z; v.w += bb.w;
                *(float4*)(P + c * H2 + k) = v;
            }
        }
        __syncthreads();
    }

    const int slb = slen[b], tlb = tlen[b];

    // ---- intra-tile wavefront ----
    for (int dd = 0; dd < 2 * TILE - 1; dd++) {
        int iilo = dd - (TILE - 1); if (iilo < 0) iilo = 0;
        int iihi = (dd < TILE - 1) ? dd : (TILE - 1);
        int cur = dd & 1, prv = cur ^ 1;

        for (int c = iilo; c <= iihi; c++) {
            int jjc = dd - c;
            const float* pa = (c > 0)   ? &HX[prv * 512 + (c - 1) * 64]
                                        : &HXtop[jjc * 64];
            const float* pb = (jjc > 0) ? &HY[prv * 512 + c * 64]
                                        : &HYleft[c * 64];
            const float* hs = ((kq < 4) ? pa : pb) + hofs;

            float a0, a1;
            {
                float4 hv = *(const float4*)(hs + co0);
                a0  = hv.x * w[0].x;  a1  = hv.x * w[0].y;
                a0 += hv.y * w[1].x;  a1 += hv.y * w[1].y;
                a0 += hv.z * w[2].x;  a1 += hv.z * w[2].y;
                a0 += hv.w * w[3].x;  a1 += hv.w * w[3].y;
            }
            {
                float4 hv = *(const float4*)(hs + co1);
                a0 += hv.x * w[4].x;  a1 += hv.x * w[4].y;
                a0 += hv.y * w[5].x;  a1 += hv.y * w[5].y;
                a0 += hv.z * w[6].x;  a1 += hv.z * w[6].y;
                a0 += hv.w * w[7].x;  a1 += hv.w * w[7].y;
            }
            {
                float4 hv = *(const float4*)(hs + co2);
                a0 += hv.x * w[8].x;  a1 += hv.x * w[8].y;
                a0 += hv.y * w[9].x;  a1 += hv.y * w[9].y;
                a0 += hv.z * w[10].x; a1 += hv.z * w[10].y;
                a0 += hv.w * w[11].x; a1 += hv.w * w[11].y;
            }
            {
                float4 hv = *(const float4*)(hs + co3);
                a0 += hv.x * w[12].x; a1 += hv.x * w[12].y;
                a0 += hv.y * w[13].x; a1 += hv.y * w[13].y;
                a0 += hv.z * w[14].x; a1 += hv.z * w[14].y;
                a0 += hv.w * w[15].x; a1 += hv.w * w[15].y;
            }

            a0 += __shfl_xor_sync(0xffffffffu, a0, 4);
            a1 += __shfl_xor_sync(0xffffffffu, a1, 4);
            a0 += __shfl_xor_sync(0xffffffffu, a0, 8);
            a1 += __shfl_xor_sync(0xffffffffu, a1, 8);
            a0 += __shfl_xor_sync(0xffffffffu, a0, 16);
            a1 += __shfl_xor_sync(0xffffffffu, a1, 16);

            if (kq == 0) {
                const float* pp = P + (c * TILE + jjc) * H2 + k0;
                float rx = ftanh(pp[0] + a0);
                float ry = ftanh(pp[1] + a1);
                int gi = i0 + c, gj = j0 + jjc;
                float2 v = make_float2(rx, ry);
                // smem ping-pong for next diagonal
                float* hp = (isx ? HX : HY) + cur * 512 + c * 64 + kb;
                *(float2*)hp = v;
                // global scratch (halos / depth-1 projections)
                float* sp = isx ? &g_hx[depth][b][gi][gj][kb]
                                : &g_hy[depth][b][gi][gj][kb];
                *(float2*)sp = v;
                // masked output
                bool m = (gi < slb) && (gj < tlb);
                int vsel = isx ? 0 : 1;
                float* op = out + ((((size_t)(vsel * 2 + depth) * Bc + b)
                                   * Sc + gi) * Tc + gj) * Hc + kb;
                float2 mv = m ? v : make_float2(0.f, 0.f);
                *(float2*)op = mv;
            }
        }
        __syncthreads();
    }
}

// ---------------------------------------------------------------------------
static inline int diag_count(int d) {
    int lo2 = d - (TG - 1); if (lo2 < 0) lo2 = 0;
    int hi2 = (d < TG - 1) ? d : (TG - 1);
    return hi2 - lo2 + 1;
}

extern "C" void kernel_launch(void* const* d_in, const int* in_sizes, int n_in,
                              void* d_out, int out_size)
{
    const float* src = (const float*)d_in[0];
    const float* trg = (const float*)d_in[1];
    const float* Wix = (const float*)d_in[2];
    const float* Whx = (const float*)d_in[3];
    const float* bx  = (const float*)d_in[4];
    const float* Wiy = (const float*)d_in[5];
    const float* Why = (const float*)d_in[6];
    const float* by  = (const float*)d_in[7];
    const int*   slen = (const int*)d_in[8];
    const int*   tlen = (const int*)d_in[9];
    float* out = (float*)d_out;

    cudaFuncSetAttribute(wave_kernel,
                         cudaFuncAttributeMaxDynamicSharedMemorySize, SMEM_BYTES);

    proj0_kernel<<<Bc * (Sc + Tc), 64>>>(src, trg, Wix, Wiy);

    // Combined wavefront: step s runs depth-0 tiles on tile-diagonal s and
    // depth-1 tiles on tile-diagonal s-1 (pipelined one step behind).
    for (int s = 0; s <= NDIAG; s++) {
        int n0 = (s < NDIAG) ? diag_count(s) : 0;
        int n1 = (s >= 1) ? diag_count(s - 1) : 0;
        int blocks = (n0 + n1) * Bc;
        if (blocks == 0) continue;
        wave_kernel<<<blocks, NTHREADS, SMEM_BYTES>>>(
            Whx, Why, bx, by, Wix, Wiy, slen, tlen, out, s, n0);
    }
}

// round 10
// speedup vs baseline: 1.3193x; 1.3193x over previous
#include <cuda_runtime.h>
#include <math.h>

#define Bc 8
#define Sc 96
#define Tc 96
#define Fc 64
#define Hc 64
#define H2 128
#define TILE 8
#define TG 12       // 96 / TILE
#define NDIAG 23    // 2*TG - 1
#define NTHREADS 512
#define H0S 68      // padded stride for depth-1 h0 staging

// Unmasked recurrence state (scratch): halos + depth-1 projections read this.
__device__ float g_hx[2][Bc][Sc][Tc][Hc];
__device__ float g_hy[2][Bc][Sc][Tc][Hc];
// Depth-0 input projections: px depends only on (b,i), py only on (b,j).
__device__ float g_px0[Bc][Sc][Hc];
__device__ float g_py0[Bc][Tc][Hc];

__device__ __forceinline__ float ftanh(float x) {
    float e = __expf(-2.0f * fabsf(x));
    float r = __fdividef(1.0f - e, 1.0f + e);
    return copysignf(r, x);
}

// ---------------------------------------------------------------------------
__global__ void proj0_kernel(const float* __restrict__ src,
                             const float* __restrict__ trg,
                             const float* __restrict__ Wix,
                             const float* __restrict__ Wiy)
{
    __shared__ float row[Fc];
    const int r = blockIdx.x;
    const int k = threadIdx.x;
    const float* W;
    const float* inrow;
    float* outp;
    if (r < Bc * Sc) {
        inrow = src + r * Fc;  W = Wix;  outp = &g_px0[0][0][0] + r * Hc;
    } else {
        int rr = r - Bc * Sc;
        inrow = trg + rr * Fc; W = Wiy;  outp = &g_py0[0][0][0] + rr * Hc;
    }
    row[k] = inrow[k];
    __syncthreads();
    float acc = 0.f;
#pragma unroll 8
    for (int f = 0; f < Fc; f++) acc += row[f] * W[f * Hc + k];
    outp[k] = acc;
}

// ---------------------------------------------------------------------------
// smem layout (floats):
//   [0      : 8192 )  STW (depth-1 prologue) / P[64][128] (depth-1, overlaid)
//                     / PXs[8][64], PYs[8][64] (depth-0, first 1024)
//   [8192   : 12544)  H0X [64][68]
//   [12544  : 16896)  H0Y [64][68]
//   [16896  : 17920)  HX  [2][8][64]
//   [17920  : 18944)  HY  [2][8][64]
//   [18944  : 19456)  HXtop  [8][64]
//   [19456  : 19968)  HYleft [8][64]
//   [19968  : 20032)  pad (guards speculative loads of the odd-tail cell)
#define SMEM_FLOATS 20032
#define SMEM_BYTES  (SMEM_FLOATS * 4)

__global__ void __launch_bounds__(NTHREADS, 1) wave_kernel(
    const float* __restrict__ Whx, const float* __restrict__ Why,
    const float* __restrict__ bx,  const float* __restrict__ by,
    const float* __restrict__ Wix, const float* __restrict__ Wiy,
    const int*   __restrict__ slen, const int* __restrict__ tlen,
    float* __restrict__ out, int s, int n0)
{
    extern __shared__ float smem[];
    float* STW    = smem;             // depth-1 staging, overlaid by P
    float* P      = smem;             // [64][128] cell-major proj (+bias)
    float* PXs    = smem;             // [8][64] depth-0 px rows (+bias)
    float* PYs    = smem + 512;       // [8][64] depth-0 py rows (+bias)
    float* H0X    = smem + 8192;      // [64][H0S]
    float* H0Y    = H0X + 64 * H0S;   // [64][H0S]
    float* HX     = H0Y + 64 * H0S;   // [2][8][64] ping-pong hx along diagonal
    float* HY     = HX + 1024;        // [2][8][64]
    float* HXtop  = HY + 1024;        // [8][64]
    float* HYleft = HXtop + 512;      // [8][64]

    const int t    = threadIdx.x;
    const int slot = blockIdx.x >> 3;
    const int b    = blockIdx.x & 7;

    int depth, diag, pos;
    if (slot < n0) { depth = 0; diag = s;     pos = slot; }
    else           { depth = 1; diag = s - 1; pos = slot - n0; }
    int lo = diag - (TG - 1); if (lo < 0) lo = 0;
    const int ti = lo + pos;
    const int tj = diag - ti;
    const int i0 = ti * TILE, j0 = tj * TILE;

    const float* bxd = bx + depth * Hc;
    const float* byd = by + depth * Hc;

    // ---- halos from neighbor tiles, zeros at grid border ----
    {
        int rr = t >> 6, k = t & 63;
        HXtop[t]  = (ti > 0) ? g_hx[depth][b][i0 - 1][j0 + rr][k] : 0.f;
        HYleft[t] = (tj > 0) ? g_hy[depth][b][i0 + rr][j0 - 1][k] : 0.f;
    }

    // ---- register-resident recurrence weights (rotated layout, as R4) ----
    const int lane = t & 31;
    const int kq   = lane >> 2;                      // 0..7 : K-slice
    const int kh   = ((t >> 5) << 2) | (lane & 3);   // 0..63 : output pair
    const int k0   = kh * 2;
    const bool isx = (kh < 32);
    const int  kb  = isx ? k0 : (k0 - Hc);
    const int  hofs = (kq & 3) * 16;
    const int  rot  = (kq + (kq >> 2)) & 3;
    const int  co0 = ((rot    ) & 3) * 4;
    const int  co1 = ((rot + 1) & 3) * 4;
    const int  co2 = ((rot + 2) & 3) * 4;
    const int  co3 = ((rot + 3) & 3) * 4;

    float2 w[16];
    {
        const float* Wbase = isx ? (Whx + depth * H2 * Hc + k0)
                                 : (Why + depth * H2 * Hc + (k0 - Hc));
#pragma unroll
        for (int u4 = 0; u4 < 4; u4++) {
            int cou = ((rot + u4) & 3) * 4;
#pragma unroll
            for (int e = 0; e < 4; e++)
                w[u4 * 4 + e] = *(const float2*)(Wbase + (kq * 16 + cou + e) * Hc);
        }
    }

    // ---- input projections ----
    if (depth == 0) {
        // tiny staging: PXs[ii][k] = px0(b,i0+ii,k)+bx ; PYs[jj][k] likewise
        int rr = t >> 6, k = t & 63;
        if (t < 512) {
            PXs[t] = g_px0[b][i0 + rr][k] + bxd[k];
            PYs[t] = g_py0[b][j0 + rr][k] + byd[k];
        }
        __syncthreads();
    } else {
        for (int idx = t; idx < 64 * H2; idx += NTHREADS) {
            int f = idx >> 7, k = idx & 127;
            STW[idx] = (k < Hc) ? Wix[Fc * Hc + f * Hc + k]
                                : Wiy[Fc * Hc + f * Hc + (k - Hc)];
        }
        for (int idx = t; idx < 64 * Fc; idx += NTHREADS) {
            int c = idx >> 6, f = idx & 63;
            int ii = c >> 3, jj = c & 7;
            H0X[c * H0S + f] = g_hx[0][b][i0 + ii][j0 + jj][f];
            H0Y[c * H0S + f] = g_hy[0][b][i0 + ii][j0 + jj][f];
        }
        __syncthreads();
        {
            const int c   = t >> 3;
            const int kb4 = (t & 7) * 4;
            float4 acc[4] = {{0,0,0,0},{0,0,0,0},{0,0,0,0},{0,0,0,0}};
            const float* HrowX = H0X + c * H0S;
            const float* HrowY = H0Y + c * H0S;
#pragma unroll 4
            for (int f = 0; f < Fc; f++) {
                float hx0 = HrowX[f];
                float hy0 = HrowY[f];
                const float* wr = STW + f * H2 + kb4;
#pragma unroll
                for (int e4 = 0; e4 < 4; e4++) {
                    float4 wv = *(const float4*)(wr + e4 * 32);
                    float hv = (e4 < 2) ? hx0 : hy0;
                    acc[e4].x += hv * wv.x; acc[e4].y += hv * wv.y;
                    acc[e4].z += hv * wv.z; acc[e4].w += hv * wv.w;
                }
            }
            __syncthreads();   // done reading STW before P overlays it
#pragma unroll
            for (int e4 = 0; e4 < 4; e4++) {
                int k = kb4 + e4 * 32;
                float4 bb;
                if (k < Hc) bb = *(const float4*)(bxd + k);
                else        bb = *(const float4*)(byd + (k - Hc));
                float4 v = acc[e4];
                v.x += bb.x; v.y += bb.y; v.z += bb.z; v.w += bb.w;
                *(float4*)(P + c * H2 + k) = v;
            }
        }
        __syncthreads();
    }

    // ---- strength-reduced epilogue bases ----
    const int slb = slen[b], tlb = tlen[b];
    float* gB = (isx ? &g_hx[depth][b][0][0][0] : &g_hy[depth][b][0][0][0]) + kb;
    float* oB = out + ((size_t)((isx ? 0 : 2) + depth) * Bc + b)
                      * ((size_t)Sc * Tc * Hc) + kb;
    float* hB = (isx ? HX : HY) + kb;
    const float* pB = (depth == 0) ? ((isx ? PXs : PYs) + kb) : (P + k0);
    const int dP = (depth == 0) ? (isx ? 64 : -64) : (7 * H2);
    const int GSTEP = (Tc - 1) * Hc;   // 6080: cell (c,jj) -> (c+1,jj-1)

    // 2-deep-accumulator dot over this thread's 16 K-rows
#define ACCUM(HS, A0, A1) do {                                              \
        float x0, y0, x1, y1;                                               \
        { float4 hv = *(const float4*)((HS) + co0);                         \
          x0 = hv.x * w[0].x;            y0 = hv.x * w[0].y;                \
          x0 = fmaf(hv.y, w[1].x, x0);   y0 = fmaf(hv.y, w[1].y, y0);       \
          x0 = fmaf(hv.z, w[2].x, x0);   y0 = fmaf(hv.z, w[2].y, y0);       \
          x0 = fmaf(hv.w, w[3].x, x0);   y0 = fmaf(hv.w, w[3].y, y0); }     \
        { float4 hv = *(const float4*)((HS) + co1);                         \
          x1 = hv.x * w[4].x;            y1 = hv.x * w[4].y;                \
          x1 = fmaf(hv.y, w[5].x, x1);   y1 = fmaf(hv.y, w[5].y, y1);       \
          x1 = fmaf(hv.z, w[6].x, x1);   y1 = fmaf(hv.z, w[6].y, y1);       \
          x1 = fmaf(hv.w, w[7].x, x1);   y1 = fmaf(hv.w, w[7].y, y1); }     \
        { float4 hv = *(const float4*)((HS) + co2);                         \
          x0 = fmaf(hv.x, w[8].x, x0);   y0 = fmaf(hv.x, w[8].y, y0);       \
          x0 = fmaf(hv.y, w[9].x, x0);   y0 = fmaf(hv.y, w[9].y, y0);       \
          x0 = fmaf(hv.z, w[10].x, x0);  y0 = fmaf(hv.z, w[10].y, y0);      \
          x0 = fmaf(hv.w, w[11].x, x0);  y0 = fmaf(hv.w, w[11].y, y0); }    \
        { float4 hv = *(const float4*)((HS) + co3);                         \
          x1 = fmaf(hv.x, w[12].x, x1);  y1 = fmaf(hv.x, w[12].y, y1);      \
          x1 = fmaf(hv.y, w[13].x, x1);  y1 = fmaf(hv.y, w[13].y, y1);      \
          x1 = fmaf(hv.z, w[14].x, x1);  y1 = fmaf(hv.z, w[14].y, y1);      \
          x1 = fmaf(hv.w, w[15].x, x1);  y1 = fmaf(hv.w, w[15].y, y1); }    \
        (A0) = x0 + x1; (A1) = y0 + y1;                                     \
    } while (0)

#define EPILOG(A0, A1, GOFF, POFF, HOFF, GI, GJ) do {                       \
        float2 pp = *(const float2*)(pB + (POFF));                          \
        float rx = ftanh(pp.x + (A0));                                      \
        float ry = ftanh(pp.y + (A1));                                      \
        float2 v = make_float2(rx, ry);                                     \
        *(float2*)(hB + (HOFF)) = v;                                        \
        *(float2*)(gB + (GOFF)) = v;                                        \
        bool m = ((GI) < slb) && ((GJ) < tlb);                              \
        float2 mv = m ? v : make_float2(0.f, 0.f);                          \
        *(float2*)(oB + (GOFF)) = mv;                                       \
    } while (0)

    // ---- intra-tile wavefront ----
    for (int dd = 0; dd < 2 * TILE - 1; dd++) {
        int iilo = dd - (TILE - 1); if (iilo < 0) iilo = 0;
        int iihi = (dd < TILE - 1) ? dd : (TILE - 1);
        int cur = dd & 1, prv = cur ^ 1;
        int hcur = cur * 512, hprv = prv * 512;
        int jj0 = dd - iilo;

        int goff = ((i0 + iilo) * Tc + (j0 + jj0)) * Hc;
        int poff = (depth == 0) ? ((isx ? iilo : jj0) * 64)
                                : ((iilo * TILE + jj0) * H2);

        for (int c = iilo; c <= iihi; c += 2) {
            int jjc  = dd - c;
            int c1   = c + 1, jjc1 = jjc - 1;
            bool has2 = (c1 <= iihi);

            const float* pa0 = (c > 0)    ? HX + hprv + (c - 1) * 64
                                          : HXtop + jjc * 64;
            const float* pb0 = (jjc > 0)  ? HY + hprv + c * 64
                                          : HYleft + c * 64;
            const float* pa1 = HX + hprv + c * 64;        // c1 >= 1 always
            const float* pb1 = (jjc1 > 0) ? HY + hprv + c1 * 64
                                          : HYleft + c1 * 64;
            const float* hs0 = ((kq < 4) ? pa0 : pb0) + hofs;
            const float* hs1 = ((kq < 4) ? pa1 : pb1) + hofs;

            float a0, a1, b0, b1;
            ACCUM(hs0, a0, a1);
            ACCUM(hs1, b0, b1);   // speculative on odd tail (pad-guarded)

            // interleaved butterfly reduction across the 8 K-slices
            a0 += __shfl_xor_sync(0xffffffffu, a0, 4);
            b0 += __shfl_xor_sync(0xffffffffu, b0, 4);
            a1 += __shfl_xor_sync(0xffffffffu, a1, 4);
            b1 += __shfl_xor_sync(0xffffffffu, b1, 4);
            a0 += __shfl_xor_sync(0xffffffffu, a0, 8);
            b0 += __shfl_xor_sync(0xffffffffu, b0, 8);
            a1 += __shfl_xor_sync(0xffffffffu, a1, 8);
            b1 += __shfl_xor_sync(0xffffffffu, b1, 8);
            a0 += __shfl_xor_sync(0xffffffffu, a0, 16);
            b0 += __shfl_xor_sync(0xffffffffu, b0, 16);
            a1 += __shfl_xor_sync(0xffffffffu, a1, 16);
            b1 += __shfl_xor_sync(0xffffffffu, b1, 16);

            if (kq == 0) {
                EPILOG(a0, a1, goff, poff, hcur + (c << 6),
                       i0 + c, j0 + jjc);
                if (has2)
                    EPILOG(b0, b1, goff + GSTEP, poff + dP, hcur + (c1 << 6),
                           i0 + c1, j0 + jjc1);
            }
            goff += 2 * GSTEP;
            poff += 2 * dP;
        }
        __syncthreads();
    }
#undef ACCUM
#undef EPILOG
}

// ---------------------------------------------------------------------------
static inline int diag_count(int d) {
    int lo2 = d - (TG - 1); if (lo2 < 0) lo2 = 0;
    int hi2 = (d < TG - 1) ? d : (TG - 1);
    return hi2 - lo2 + 1;
}

extern "C" void kernel_launch(void* const* d_in, const int* in_sizes, int n_in,
                              void* d_out, int out_size)
{
    const float* src = (const float*)d_in[0];
    const float* trg = (const float*)d_in[1];
    const float* Wix = (const float*)d_in[2];
    const float* Whx = (const float*)d_in[3];
    const float* bx  = (const float*)d_in[4];
    const float* Wiy = (const float*)d_in[5];
    const float* Why = (const float*)d_in[6];
    const float* by  = (const float*)d_in[7];
    const int*   slen = (const int*)d_in[8];
    const int*   tlen = (const int*)d_in[9];
    float* out = (float*)d_out;

    cudaFuncSetAttribute(wave_kernel,
                         cudaFuncAttributeMaxDynamicSharedMemorySize, SMEM_BYTES);

    proj0_kernel<<<Bc * (Sc + Tc), 64>>>(src, trg, Wix, Wiy);

    for (int s = 0; s <= NDIAG; s++) {
        int n0 = (s < NDIAG) ? diag_count(s) : 0;
        int n1 = (s >= 1) ? diag_count(s - 1) : 0;
        int blocks = (n0 + n1) * Bc;
        if (blocks == 0) continue;
        wave_kernel<<<blocks, NTHREADS, SMEM_BYTES>>>(
            Whx, Why, bx, by, Wix, Wiy, slen, tlen, out, s, n0);
    }
}

// round 13
// speedup vs baseline: 1.6770x; 1.2711x over previous
#include <cuda_runtime.h>
#include <math.h>
#include <stdint.h>

#define Bc 8
#define Sc 96
#define Tc 96
#define Fc 64
#define Hc 64
#define H2 128
#define TILE 8
#define TG 12       // 96 / TILE
#define NDIAG 23    // 2*TG - 1
#define NTHREADS 512
#define GSTEP 6080  // (Tc-1)*Hc : cell (c,jj) -> (c+1,jj-1)

// Unmasked recurrence state (scratch): halos read this.
__device__ float g_hx[2][Bc][Sc][Tc][Hc];
__device__ float g_hy[2][Bc][Sc][Tc][Hc];
// Depth-0 input projections.
__device__ float g_px0[Bc][Sc][Hc];
__device__ float g_py0[Bc][Tc][Hc];
// Depth-1 per-cell input projections (bias folded), produced by d0 CTA tails.
__device__ float g_P1[Bc][TG][TG][64][H2];

__device__ __forceinline__ float ftanh(float x) {
    float e = __expf(-2.0f * fabsf(x));
    float r = __fdividef(1.0f - e, 1.0f + e);
    return copysignf(r, x);
}

// ---- packed f32x2 helpers (Blackwell) ----
#define FMA2(acc, a, b) asm("fma.rn.f32x2 %0, %1, %2, %0;" : "+l"(acc) : "l"(a), "l"(b))
#define MUL2(d, a, b)   asm("mul.rn.f32x2 %0, %1, %2;"     : "=l"(d)  : "l"(a), "l"(b))
#define ADD2(d, a, b)   asm("add.rn.f32x2 %0, %1, %2;"     : "=l"(d)  : "l"(a), "l"(b))
#define PACK2(d, lo, hi) asm("mov.b64 %0, {%1, %2};" : "=l"(d) : "f"(lo), "f"(hi))
#define UNPK2(lo, hi, s) asm("mov.b64 {%0, %1}, %2;" : "=f"(lo), "=f"(hi) : "l"(s))
#define LDSV2(a, b_, addr) \
    asm volatile("ld.shared.v2.b64 {%0, %1}, [%2];" : "=l"(a), "=l"(b_) : "r"(addr))

// ---------------------------------------------------------------------------
__global__ void proj0_kernel(const float* __restrict__ src,
                             const float* __restrict__ trg,
                             const float* __restrict__ Wix,
                             const float* __restrict__ Wiy)
{
    __shared__ float row[Fc];
    const int r = blockIdx.x;
    const int k = threadIdx.x;
    const float* W;
    const float* inrow;
    float* outp;
    if (r < Bc * Sc) {
        inrow = src + r * Fc;  W = Wix;  outp = &g_px0[0][0][0] + r * Hc;
    } else {
        int rr = r - Bc * Sc;
        inrow = trg + rr * Fc; W = Wiy;  outp = &g_py0[0][0][0] + rr * Hc;
    }
    row[k] = inrow[k];
    __syncthreads();
    float acc = 0.f;
#pragma unroll 8
    for (int f = 0; f < Fc; f++) acc += row[f] * W[f * Hc + k];
    outp[k] = acc;
}

// ---------------------------------------------------------------------------
// smem layout (floats):
//   [0     : 1024 )  d0: PXs[8][64], PYs[8][64]    | d1: P[64][128] (0..8192)
//   [1024  : 9216 )  d0: STW [64][128] (Wi depth1) | (covered by d1 P)
//   [9216  : 13568)  d0: HXF [64][68]  full-tile hx outputs
//   [13568 : 17920)  d0: HYF [64][68]
//   [17920 : 18944)  HX [2][8][64]
//   [18944 : 19968)  HY [2][8][64]
//   [19968 : 20480)  HXtop [8][64]
//   [20480 : 20992)  HYleft [8][64]
//   [20992 : 21504)  pad (speculative-read guard)
#define SMEM_FLOATS 21504
#define SMEM_BYTES  (SMEM_FLOATS * 4)

__global__ void __launch_bounds__(NTHREADS, 1) wave_kernel(
    const float* __restrict__ Whx, const float* __restrict__ Why,
    const float* __restrict__ bx,  const float* __restrict__ by,
    const float* __restrict__ Wix, const float* __restrict__ Wiy,
    const int*   __restrict__ slen, const int* __restrict__ tlen,
    float* __restrict__ out, int s, int n0)
{
    extern __shared__ float smem[];
    float* P      = smem;             // d1 only
    float* PXs    = smem;             // d0
    float* PYs    = smem + 512;       // d0
    float* STW    = smem + 1024;      // d0
    float* HXF    = smem + 9216;      // d0
    float* HYF    = smem + 13568;     // d0
    float* HX     = smem + 17920;
    float* HY     = smem + 18944;
    float* HXtop  = smem + 19968;
    float* HYleft = smem + 20480;

    const uint32_t uHX     = (uint32_t)__cvta_generic_to_shared(HX);
    const uint32_t uHY     = (uint32_t)__cvta_generic_to_shared(HY);
    const uint32_t uHXtop  = (uint32_t)__cvta_generic_to_shared(HXtop);
    const uint32_t uHYleft = (uint32_t)__cvta_generic_to_shared(HYleft);

    const int t    = threadIdx.x;
    const int slot = blockIdx.x >> 3;
    const int b    = blockIdx.x & 7;

    int depth, diag, pos;
    if (slot < n0) { depth = 0; diag = s;     pos = slot; }
    else           { depth = 1; diag = s - 1; pos = slot - n0; }
    int lo = diag - (TG - 1); if (lo < 0) lo = 0;
    const int ti = lo + pos;
    const int tj = diag - ti;
    const int i0 = ti * TILE, j0 = tj * TILE;

    const float* bxd = bx + depth * Hc;
    const float* byd = by + depth * Hc;

    // ---- halos from neighbor tiles, zeros at grid border ----
    {
        int rr = t >> 6, k = t & 63;
        HXtop[t]  = (ti > 0) ? g_hx[depth][b][i0 - 1][j0 + rr][k] : 0.f;
        HYleft[t] = (tj > 0) ? g_hy[depth][b][i0 + rr][j0 - 1][k] : 0.f;
    }

    // ---- per-thread identity ----
    const int lane = t & 31;
    const int kq   = lane >> 2;                      // 0..7 : K-slice
    const int kh   = ((t >> 5) << 2) | (lane & 3);   // 0..63 : output pair
    const int k0   = kh * 2;
    const bool isx = (kh < 32);
    const int  kb  = isx ? k0 : (k0 - Hc);
    const int  hofsB = (kq & 3) * 64;                // byte offset of 16-float slice
    const int  rot   = (kq + (kq >> 2)) & 3;
    const int  cob0 = ((rot    ) & 3) * 16;          // chunk byte offsets in slice
    const int  cob1 = ((rot + 1) & 3) * 16;
    const int  cob2 = ((rot + 2) & 3) * 16;
    const int  cob3 = ((rot + 3) & 3) * 16;

    // ---- register weights: packed pairs, rotated chunk order ----
    unsigned long long wxx[8], wyy[8];
    {
        const float* Wbase = isx ? (Whx + depth * H2 * Hc + k0)
                                 : (Why + depth * H2 * Hc + (k0 - Hc));
#pragma unroll
        for (int u = 0; u < 4; u++) {
            int cou = ((rot + u) & 3) * 4;
            int r = kq * 16 + cou;
            float2 wa = *(const float2*)(Wbase + (r + 0) * Hc);
            float2 wb = *(const float2*)(Wbase + (r + 1) * Hc);
            float2 wc = *(const float2*)(Wbase + (r + 2) * Hc);
            float2 wd = *(const float2*)(Wbase + (r + 3) * Hc);
            PACK2(wxx[2*u],   wa.x, wb.x);  PACK2(wyy[2*u],   wa.y, wb.y);
            PACK2(wxx[2*u+1], wc.x, wd.x);  PACK2(wyy[2*u+1], wc.y, wd.y);
        }
    }

    // ---- input projections ----
    if (depth == 0) {
        int rr = t >> 6, k = t & 63;
        PXs[t] = g_px0[b][i0 + rr][k] + bxd[k];
        PYs[t] = g_py0[b][j0 + rr][k] + byd[k];
        // stage depth-1 Wi for the projection tail
        for (int idx = t; idx < 64 * H2; idx += NTHREADS) {
            int f = idx >> 7, k2 = idx & 127;
            STW[idx] = (k2 < Hc) ? Wix[Fc * Hc + f * Hc + k2]
                                 : Wiy[Fc * Hc + f * Hc + (k2 - Hc)];
        }
    } else {
        // P precomputed by the depth-0 CTA of this tile (previous launch)
        const float4* s4 = (const float4*)&g_P1[b][ti][tj][0][0];
        float4* d4 = (float4*)P;
        for (int idx = t; idx < 2048; idx += NTHREADS) d4[idx] = s4[idx];
    }
    __syncthreads();

    // ---- epilogue bases ----
    const int slb = slen[b], tlb = tlen[b];
    float* gB = (isx ? &g_hx[depth][b][0][0][0] : &g_hy[depth][b][0][0][0]) + kb;
    float* oB = out + ((size_t)((isx ? 0 : 2) + depth) * Bc + b)
                      * ((size_t)Sc * Tc * Hc) + kb;
    float* hB = (isx ? HX : HY) + kb;
    float* hF = (isx ? HXF : HYF) + kb;
    const float* pB = (depth == 0) ? ((isx ? PXs : PYs) + kb) : (P + k0);
    const int dPc = (depth == 0) ? (isx ? 64 : -64) : (7 * H2);
    const bool evenkq = ((kq & 1) == 0);
    const int  qown   = kq >> 1;

#define ACCPK(HSADDR, AX, AY) do {                                            \
        unsigned long long _h01,_h23,_ax,_ay,_bx2,_by2;                       \
        LDSV2(_h01,_h23,(HSADDR) + cob0);                                     \
        MUL2(_ax,_h01,wxx[0]);  MUL2(_ay,_h01,wyy[0]);                        \
        FMA2(_ax,_h23,wxx[1]);  FMA2(_ay,_h23,wyy[1]);                        \
        LDSV2(_h01,_h23,(HSADDR) + cob1);                                     \
        MUL2(_bx2,_h01,wxx[2]); MUL2(_by2,_h01,wyy[2]);                       \
        FMA2(_bx2,_h23,wxx[3]); FMA2(_by2,_h23,wyy[3]);                       \
        LDSV2(_h01,_h23,(HSADDR) + cob2);                                     \
        FMA2(_ax,_h01,wxx[4]);  FMA2(_ay,_h01,wyy[4]);                        \
        FMA2(_ax,_h23,wxx[5]);  FMA2(_ay,_h23,wyy[5]);                        \
        LDSV2(_h01,_h23,(HSADDR) + cob3);                                     \
        FMA2(_bx2,_h01,wxx[6]); FMA2(_by2,_h01,wyy[6]);                       \
        FMA2(_bx2,_h23,wxx[7]); FMA2(_by2,_h23,wyy[7]);                       \
        ADD2(_ax,_ax,_bx2); ADD2(_ay,_ay,_by2);                               \
        float _l,_h;                                                          \
        UNPK2(_l,_h,_ax); AX = _l + _h;                                       \
        UNPK2(_l,_h,_ay); AY = _l + _h;                                       \
    } while (0)

    // ---- intra-tile wavefront ----
    for (int dd = 0; dd < 2 * TILE - 1; dd++) {
        int iilo = dd - (TILE - 1); if (iilo < 0) iilo = 0;
        int iihi = (dd < TILE - 1) ? dd : (TILE - 1);
        int cur = dd & 1, prv = cur ^ 1;
        int hcur = cur * 512, hprvB = prv * 2048;    // bytes for prv

        for (int cb = iilo; cb <= iihi; cb += 4) {
            uint32_t hs0, hs1, hs2, hs3;
#pragma unroll
            for (int q = 0; q < 4; q++) {
                int cq = cb + q, jjq = dd - cq;
                uint32_t pa = (cq > 0)  ? uHX + hprvB + (cq - 1) * 256
                                        : uHXtop + jjq * 256;
                uint32_t pb = (jjq > 0) ? uHY + hprvB + cq * 256
                                        : uHYleft + cq * 256;
                uint32_t hq = ((kq < 4) ? pa : pb) + hofsB;
                if (q == 0) hs0 = hq; else if (q == 1) hs1 = hq;
                else if (q == 2) hs2 = hq; else hs3 = hq;
            }
            float ax0,ay0,ax1,ay1,ax2,ay2,ax3,ay3;
            ACCPK(hs0, ax0, ay0);
            ACCPK(hs1, ax1, ay1);
            ACCPK(hs2, ax2, ay2);
            ACCPK(hs3, ax3, ay3);

            // reduce-scatter across the 8 kq groups: group g owns
            // (cell = cb + (g>>1), comp = g&1)
            const unsigned FULL = 0xffffffffu;
            bool hi2 = (kq & 4);
            float sv, rv, t0, t1, t2, t3, v0, v1, wv, ov;
            sv = hi2 ? ax0 : ax2; rv = __shfl_xor_sync(FULL, sv, 16);
            t0 = (hi2 ? ax2 : ax0) + rv;
            sv = hi2 ? ay0 : ay2; rv = __shfl_xor_sync(FULL, sv, 16);
            t1 = (hi2 ? ay2 : ay0) + rv;
            sv = hi2 ? ax1 : ax3; rv = __shfl_xor_sync(FULL, sv, 16);
            t2 = (hi2 ? ax3 : ax1) + rv;
            sv = hi2 ? ay1 : ay3; rv = __shfl_xor_sync(FULL, sv, 16);
            t3 = (hi2 ? ay3 : ay1) + rv;
            bool b1 = (kq & 2);
            sv = b1 ? t0 : t2; rv = __shfl_xor_sync(FULL, sv, 8);
            v0 = (b1 ? t2 : t0) + rv;
            sv = b1 ? t1 : t3; rv = __shfl_xor_sync(FULL, sv, 8);
            v1 = (b1 ? t3 : t1) + rv;
            bool b0 = (kq & 1);
            sv = b0 ? v0 : v1; rv = __shfl_xor_sync(FULL, sv, 4);
            wv = (b0 ? v1 : v0) + rv;
            ov = __shfl_xor_sync(FULL, wv, 4);

            // branchless distributed epilogue (even-kq groups store)
            {
                int cq = cb + qown, jjq = dd - cq;
                bool act = (cq <= iihi);
                int pof_base = (depth == 0)
                             ? ((isx ? cb : (dd - cb)) * 64)
                             : ((cb * TILE + (dd - cb)) * H2);
                int pof = act ? (pof_base + qown * dPc) : 0;
                float2 pp = *(const float2*)(pB + pof);
                float rx = ftanh(pp.x + wv);
                float ry = ftanh(pp.y + ov);
                if (act && evenkq) {
                    float2 v = make_float2(rx, ry);
                    *(float2*)(hB + hcur + cq * 64) = v;
                    int go = ((i0 + cq) * Tc + (j0 + jjq)) * Hc;
                    *(float2*)(gB + go) = v;
                    if (depth == 0)
                        *(float2*)(hF + (cq * TILE + jjq) * 68) = v;
                    bool m = ((i0 + cq) < slb) && ((j0 + jjq) < tlb);
                    float2 mv = m ? v : make_float2(0.f, 0.f);
                    *(float2*)(oB + go) = mv;
                }
            }
        }
        __syncthreads();
    }
#undef ACCPK

    // ---- depth-0 tail: projection GEMM P1 = h0 @ Wi[1] + b[1] -> g_P1 ----
    if (depth == 0) {
        const int c   = t >> 3;            // cell 0..63
        const int kb4 = (t & 7) * 4;
        unsigned long long acc[8];
#pragma unroll
        for (int i = 0; i < 8; i++) acc[i] = 0ull;
        const uint32_t uW  = (uint32_t)__cvta_generic_to_shared(STW) + kb4 * 4;
        const float* HrX = HXF + c * 68;
        const float* HrY = HYF + c * 68;
#pragma unroll 4
        for (int f = 0; f < Fc; f++) {
            unsigned long long hxd, hyd, w0, w1;
            float hx0 = HrX[f], hy0 = HrY[f];
            PACK2(hxd, hx0, hx0);
            PACK2(hyd, hy0, hy0);
            uint32_t wrow = uW + f * 512;
#pragma unroll
            for (int e4 = 0; e4 < 4; e4++) {
                LDSV2(w0, w1, wrow + e4 * 128);
                unsigned long long hd = (e4 < 2) ? hxd : hyd;
                FMA2(acc[2*e4],     hd, w0);
                FMA2(acc[2*e4 + 1], hd, w1);
            }
        }
        float* dst = &g_P1[b][ti][tj][0][0] + c * H2;
#pragma unroll
        for (int e4 = 0; e4 < 4; e4++) {
            int k = kb4 + e4 * 32;
            float4 bb = (k < Hc) ? *(const float4*)(bx + Hc + k)
                                 : *(const float4*)(by + k);   // by + Hc + (k-Hc)
            float p0, p1, p2, p3;
            UNPK2(p0, p1, acc[2*e4]);
            UNPK2(p2, p3, acc[2*e4 + 1]);
            float4 v = make_float4(p0 + bb.x, p1 + bb.y, p2 + bb.z, p3 + bb.w);
            *(float4*)(dst + k) = v;
        }
    }
}

// ---------------------------------------------------------------------------
static inline int diag_count(int d) {
    int lo2 = d - (TG - 1); if (lo2 < 0) lo2 = 0;
    int hi2 = (d < TG - 1) ? d : (TG - 1);
    return hi2 - lo2 + 1;
}

extern "C" void kernel_launch(void* const* d_in, const int* in_sizes, int n_in,
                              void* d_out, int out_size)
{
    const float* src = (const float*)d_in[0];
    const float* trg = (const float*)d_in[1];
    const float* Wix = (const float*)d_in[2];
    const float* Whx = (const float*)d_in[3];
    const float* bx  = (const float*)d_in[4];
    const float* Wiy = (const float*)d_in[5];
    const float* Why = (const float*)d_in[6];
    const float* by  = (const float*)d_in[7];
    const int*   slen = (const int*)d_in[8];
    const int*   tlen = (const int*)d_in[9];
    float* out = (float*)d_out;

    cudaFuncSetAttribute(wave_kernel,
                         cudaFuncAttributeMaxDynamicSharedMemorySize, SMEM_BYTES);

    proj0_kernel<<<Bc * (Sc + Tc), 64>>>(src, trg, Wix, Wiy);

    for (int ss = 0; ss <= NDIAG; ss++) {
        int nn0 = (ss < NDIAG) ? diag_count(ss) : 0;
        int nn1 = (ss >= 1) ? diag_count(ss - 1) : 0;
        int blocks = (nn0 + nn1) * Bc;
        if (blocks == 0) continue;
        wave_kernel<<<blocks, NTHREADS, SMEM_BYTES>>>(
            Whx, Why, bx, by, Wix, Wiy, slen, tlen, out, ss, nn0);
    }
}

// round 14
// speedup vs baseline: 1.7002x; 1.0139x over previous
#include <cuda_runtime.h>
#include <math.h>
#include <stdint.h>

#define Bc 8
#define Sc 96
#define Tc 96
#define Fc 64
#define Hc 64
#define H2 128
#define TILE 8
#define TG 12       // 96 / TILE
#define NDIAG 23    // 2*TG - 1
#define NTHREADS 512

// Unmasked recurrence state (scratch): halos read this (border cells only).
__device__ float g_hx[2][Bc][Sc][Tc][Hc];
__device__ float g_hy[2][Bc][Sc][Tc][Hc];
// Depth-0 input projections.
__device__ float g_px0[Bc][Sc][Hc];
__device__ float g_py0[Bc][Tc][Hc];
// Depth-1 per-cell input projections (bias folded), produced by d0 CTA tails.
__device__ float g_P1[Bc][TG][TG][64][H2];

__device__ __forceinline__ float ftanh(float x) {
    float e = __expf(-2.0f * fabsf(x));
    float r = __fdividef(1.0f - e, 1.0f + e);
    return copysignf(r, x);
}

// ---- packed f32x2 helpers (Blackwell) ----
#define FMA2(acc, a, b) asm("fma.rn.f32x2 %0, %1, %2, %0;" : "+l"(acc) : "l"(a), "l"(b))
#define MUL2(d, a, b)   asm("mul.rn.f32x2 %0, %1, %2;"     : "=l"(d)  : "l"(a), "l"(b))
#define ADD2(d, a, b)   asm("add.rn.f32x2 %0, %1, %2;"     : "=l"(d)  : "l"(a), "l"(b))
#define PACK2(d, lo, hi) asm("mov.b64 %0, {%1, %2};" : "=l"(d) : "f"(lo), "f"(hi))
#define UNPK2(lo, hi, s) asm("mov.b64 {%0, %1}, %2;" : "=f"(lo), "=f"(hi) : "l"(s))
#define LDSV2(a, b_, addr) \
    asm volatile("ld.shared.v2.b64 {%0, %1}, [%2];" : "=l"(a), "=l"(b_) : "r"(addr))

// ---------------------------------------------------------------------------
__global__ void proj0_kernel(const float* __restrict__ src,
                             const float* __restrict__ trg,
                             const float* __restrict__ Wix,
                             const float* __restrict__ Wiy)
{
    __shared__ float row[Fc];
    const int r = blockIdx.x;
    const int k = threadIdx.x;
    const float* W;
    const float* inrow;
    float* outp;
    if (r < Bc * Sc) {
        inrow = src + r * Fc;  W = Wix;  outp = &g_px0[0][0][0] + r * Hc;
    } else {
        int rr = r - Bc * Sc;
        inrow = trg + rr * Fc; W = Wiy;  outp = &g_py0[0][0][0] + rr * Hc;
    }
    row[k] = inrow[k];
    __syncthreads();
    float acc = 0.f;
#pragma unroll 8
    for (int f = 0; f < Fc; f++) acc += row[f] * W[f * Hc + k];
    outp[k] = acc;
}

// ---------------------------------------------------------------------------
// smem layout (floats):
//   [0     : 1024 )  d0: PXs[8][64], PYs[8][64]
//   [1024  : 9216 )  d0: STW [64][128] (Wi depth1)
//   [9216  : 13568)  d0: HXF [64][68]  full-tile hx outputs
//   [13568 : 17920)  d0: HYF [64][68]
//   [17920 : 18944)  HX [2][8][64]
//   [18944 : 19968)  HY [2][8][64]
//   [19968 : 20480)  HXtop [8][64]
//   [20480 : 20992)  HYleft [8][64]
//   [20992 : 21504)  pad (speculative-read guard)
#define SMEM_FLOATS 21504
#define SMEM_BYTES  (SMEM_FLOATS * 4)

__global__ void __launch_bounds__(NTHREADS, 1) wave_kernel(
    const float* __restrict__ Whx, const float* __restrict__ Why,
    const float* __restrict__ bx,  const float* __restrict__ by,
    const float* __restrict__ Wix, const float* __restrict__ Wiy,
    const int*   __restrict__ slen, const int* __restrict__ tlen,
    float* __restrict__ out, int s, int n0)
{
    extern __shared__ float smem[];
    float* PXs    = smem;             // d0
    float* PYs    = smem + 512;       // d0
    float* STW    = smem + 1024;      // d0
    float* HXF    = smem + 9216;      // d0
    float* HYF    = smem + 13568;     // d0
    float* HX     = smem + 17920;
    float* HY     = smem + 18944;
    float* HXtop  = smem + 19968;
    float* HYleft = smem + 20480;

    const uint32_t uHX     = (uint32_t)__cvta_generic_to_shared(HX);
    const uint32_t uHY     = (uint32_t)__cvta_generic_to_shared(HY);
    const uint32_t uHXtop  = (uint32_t)__cvta_generic_to_shared(HXtop);
    const uint32_t uHYleft = (uint32_t)__cvta_generic_to_shared(HYleft);

    const int t    = threadIdx.x;
    const int slot = blockIdx.x >> 3;
    const int b    = blockIdx.x & 7;

    int depth, diag, pos;
    if (slot < n0) { depth = 0; diag = s;     pos = slot; }
    else           { depth = 1; diag = s - 1; pos = slot - n0; }
    int lo = diag - (TG - 1); if (lo < 0) lo = 0;
    const int ti = lo + pos;
    const int tj = diag - ti;
    const int i0 = ti * TILE, j0 = tj * TILE;

    const float* bxd = bx + depth * Hc;
    const float* byd = by + depth * Hc;

    // ---- halos from neighbor tiles (border cells), zeros at grid border ----
    {
        int rr = t >> 6, k = t & 63;
        HXtop[t]  = (ti > 0) ? g_hx[depth][b][i0 - 1][j0 + rr][k] : 0.f;
        HYleft[t] = (tj > 0) ? g_hy[depth][b][i0 + rr][j0 - 1][k] : 0.f;
    }

    // ---- per-thread identity ----
    const int lane = t & 31;
    const int kq   = lane >> 2;                      // 0..7 : K-slice
    const int kh   = ((t >> 5) << 2) | (lane & 3);   // 0..63 : output pair
    const int k0   = kh * 2;
    const bool isx = (kh < 32);
    const int  kb  = isx ? k0 : (k0 - Hc);
    const int  hofsB = (kq & 3) * 64;                // byte offset of 16-float slice
    const int  rot   = (kq + (kq >> 2)) & 3;
    const int  cob0 = ((rot    ) & 3) * 16;
    const int  cob1 = ((rot + 1) & 3) * 16;
    const int  cob2 = ((rot + 2) & 3) * 16;
    const int  cob3 = ((rot + 3) & 3) * 16;

    // ---- register weights: packed pairs, rotated chunk order ----
    unsigned long long wxx[8], wyy[8];
    {
        const float* Wbase = isx ? (Whx + depth * H2 * Hc + k0)
                                 : (Why + depth * H2 * Hc + (k0 - Hc));
#pragma unroll
        for (int u = 0; u < 4; u++) {
            int cou = ((rot + u) & 3) * 4;
            int r = kq * 16 + cou;
            float2 wa = *(const float2*)(Wbase + (r + 0) * Hc);
            float2 wb = *(const float2*)(Wbase + (r + 1) * Hc);
            float2 wc = *(const float2*)(Wbase + (r + 2) * Hc);
            float2 wd = *(const float2*)(Wbase + (r + 3) * Hc);
            PACK2(wxx[2*u],   wa.x, wb.x);  PACK2(wyy[2*u],   wa.y, wb.y);
            PACK2(wxx[2*u+1], wc.x, wd.x);  PACK2(wyy[2*u+1], wc.y, wd.y);
        }
    }

    // ---- input projections ----
    if (depth == 0) {
        int rr = t >> 6, k = t & 63;
        PXs[t] = g_px0[b][i0 + rr][k] + bxd[k];
        PYs[t] = g_py0[b][j0 + rr][k] + byd[k];
        // stage depth-1 Wi for the projection tail
        for (int idx = t; idx < 64 * H2; idx += NTHREADS) {
            int f = idx >> 7, k2 = idx & 127;
            STW[idx] = (k2 < Hc) ? Wix[Fc * Hc + f * Hc + k2]
                                 : Wiy[Fc * Hc + f * Hc + (k2 - Hc)];
        }
    }
    // depth-1: P read directly from g_P1 (L2-hot), no smem copy
    __syncthreads();

    // ---- epilogue bases ----
    const int slb = slen[b], tlb = tlen[b];
    float* gB = (isx ? &g_hx[depth][b][0][0][0] : &g_hy[depth][b][0][0][0]) + kb;
    float* oB = out + ((size_t)((isx ? 0 : 2) + depth) * Bc + b)
                      * ((size_t)Sc * Tc * Hc) + kb;
    float* hB = (isx ? HX : HY) + kb;
    float* hF = (isx ? HXF : HYF) + kb;
    const float* pB = (depth == 0) ? ((isx ? PXs : PYs) + kb)
                                   : (&g_P1[b][ti][tj][0][0] + k0);
    const int dPc = (depth == 0) ? (isx ? 64 : -64) : (7 * H2);
    const bool evenkq = ((kq & 1) == 0);
    const int  qown   = kq >> 1;

#define ACCPK(HSADDR, AX, AY) do {                                            \
        unsigned long long _h01,_h23,_ax,_ay,_bx2,_by2;                       \
        LDSV2(_h01,_h23,(HSADDR) + cob0);                                     \
        MUL2(_ax,_h01,wxx[0]);  MUL2(_ay,_h01,wyy[0]);                        \
        FMA2(_ax,_h23,wxx[1]);  FMA2(_ay,_h23,wyy[1]);                        \
        LDSV2(_h01,_h23,(HSADDR) + cob1);                                     \
        MUL2(_bx2,_h01,wxx[2]); MUL2(_by2,_h01,wyy[2]);                       \
        FMA2(_bx2,_h23,wxx[3]); FMA2(_by2,_h23,wyy[3]);                       \
        LDSV2(_h01,_h23,(HSADDR) + cob2);                                     \
        FMA2(_ax,_h01,wxx[4]);  FMA2(_ay,_h01,wyy[4]);                        \
        FMA2(_ax,_h23,wxx[5]);  FMA2(_ay,_h23,wyy[5]);                        \
        LDSV2(_h01,_h23,(HSADDR) + cob3);                                     \
        FMA2(_bx2,_h01,wxx[6]); FMA2(_by2,_h01,wyy[6]);                       \
        FMA2(_bx2,_h23,wxx[7]); FMA2(_by2,_h23,wyy[7]);                       \
        ADD2(_ax,_ax,_bx2); ADD2(_ay,_ay,_by2);                               \
        float _l,_h;                                                          \
        UNPK2(_l,_h,_ax); AX = _l + _h;                                       \
        UNPK2(_l,_h,_ay); AY = _l + _h;                                       \
    } while (0)

// compute the 4 h-slice smem addresses for a quad starting at cell CB
#define QADDR(CB, H0, H1, H2_, H3) do {                                       \
        _Pragma("unroll")                                                     \
        for (int q = 0; q < 4; q++) {                                         \
            int cq = (CB) + q, jjq = dd - cq;                                 \
            uint32_t pa = (cq > 0)  ? uHX + hprvB + (cq - 1) * 256            \
                                    : uHXtop + jjq * 256;                     \
            uint32_t pb = (jjq > 0) ? uHY + hprvB + cq * 256                  \
                                    : uHYleft + cq * 256;                     \
            uint32_t hq = ((kq < 4) ? pa : pb) + hofsB;                       \
            if (q == 0) H0 = hq; else if (q == 1) H1 = hq;                    \
            else if (q == 2) H2_ = hq; else H3 = hq;                          \
        }                                                                     \
    } while (0)

// reduce-scatter across the 8 kq groups: group g owns (cell CB+(g>>1), comp g&1)
#define RTREE(AX0,AY0,AX1,AY1,AX2,AY2,AX3,AY3, WV, OV) do {                   \
        const unsigned FULL = 0xffffffffu;                                    \
        bool hi2 = (kq & 4);                                                  \
        float sv, rv, t0, t1, t2, t3, v0, v1;                                 \
        sv = hi2 ? AX0 : AX2; rv = __shfl_xor_sync(FULL, sv, 16);             \
        t0 = (hi2 ? AX2 : AX0) + rv;                                          \
        sv = hi2 ? AY0 : AY2; rv = __shfl_xor_sync(FULL, sv, 16);             \
        t1 = (hi2 ? AY2 : AY0) + rv;                                          \
        sv = hi2 ? AX1 : AX3; rv = __shfl_xor_sync(FULL, sv, 16);             \
        t2 = (hi2 ? AX3 : AX1) + rv;                                          \
        sv = hi2 ? AY1 : AY3; rv = __shfl_xor_sync(FULL, sv, 16);             \
        t3 = (hi2 ? AY3 : AY1) + rv;                                          \
        bool b1 = (kq & 2);                                                   \
        sv = b1 ? t0 : t2; rv = __shfl_xor_sync(FULL, sv, 8);                 \
        v0 = (b1 ? t2 : t0) + rv;                                             \
        sv = b1 ? t1 : t3; rv = __shfl_xor_sync(FULL, sv, 8);                 \
        v1 = (b1 ? t3 : t1) + rv;                                             \
        bool b0 = (kq & 1);                                                   \
        sv = b0 ? v0 : v1; rv = __shfl_xor_sync(FULL, sv, 4);                 \
        WV = (b0 ? v1 : v0) + rv;                                             \
        OV = __shfl_xor_sync(FULL, WV, 4);                                    \
    } while (0)

#define EPILOG2(WV, OV, PP, ACT, CQ, JJQ) do {                                \
        float rx = ftanh((PP).x + (WV));                                      \
        float ry = ftanh((PP).y + (OV));                                      \
        if ((ACT) && evenkq) {                                                \
            float2 v = make_float2(rx, ry);                                   \
            *(float2*)(hB + hcur + (CQ) * 64) = v;                            \
            int go = ((i0 + (CQ)) * Tc + (j0 + (JJQ))) * Hc;                  \
            if (depth == 0)                                                   \
                *(float2*)(hF + ((CQ) * TILE + (JJQ)) * 68) = v;              \
            if ((CQ) == TILE - 1 || (JJQ) == TILE - 1)                        \
                *(float2*)(gB + go) = v;                                      \
            bool m = ((i0 + (CQ)) < slb) && ((j0 + (JJQ)) < tlb);             \
            float2 mv = m ? v : make_float2(0.f, 0.f);                        \
            *(float2*)(oB + go) = mv;                                         \
        }                                                                     \
    } while (0)

    // ---- intra-tile wavefront: ONE straight-line region per diagonal ----
    for (int dd = 0; dd < 2 * TILE - 1; dd++) {
        int iilo = dd - (TILE - 1); if (iilo < 0) iilo = 0;
        int iihi = (dd < TILE - 1) ? dd : (TILE - 1);
        int cur = dd & 1, prv = cur ^ 1;
        int hcur = cur * 512, hprvB = prv * 2048;

        const int  cbA  = iilo;
        const bool twoQ = (iihi - iilo) >= 4;

        // quad A: ownership + prefetch pp
        int  cqA  = cbA + qown, jjqA = dd - cqA;
        bool actA = (cqA <= iihi);
        int  pofA_base = (depth == 0) ? ((isx ? cbA : (dd - cbA)) * 64)
                                      : ((cbA * TILE + (dd - cbA)) * H2);
        int  pofA = actA ? (pofA_base + qown * dPc) : 0;
        float2 ppA = *(const float2*)(pB + pofA);

        // quad B: ownership + prefetch pp (act-guarded -> safe when !twoQ)
        const int cbB = cbA + 4;
        int  cqB  = cbB + qown, jjqB = dd - cqB;
        bool actB = (cqB <= iihi);
        int  pofB_base = (depth == 0) ? ((isx ? cbB : (dd - cbB)) * 64)
                                      : ((cbB * TILE + (dd - cbB)) * H2);
        int  pofB = actB ? (pofB_base + qown * dPc) : 0;
        float2 ppB = *(const float2*)(pB + pofB);

        uint32_t ha0, ha1, ha2, ha3;
        QADDR(cbA, ha0, ha1, ha2, ha3);

        float ax0,ay0,ax1,ay1,ax2,ay2,ax3,ay3;
        ACCPK(ha0, ax0, ay0);
        ACCPK(ha1, ax1, ay1);
        ACCPK(ha2, ax2, ay2);
        ACCPK(ha3, ax3, ay3);

        if (twoQ) {
            uint32_t hb0, hb1, hb2, hb3;
            QADDR(cbB, hb0, hb1, hb2, hb3);
            float bx0,by0,bx1,by1,bx2,by2,bx3,by3;
            ACCPK(hb0, bx0, by0);
            ACCPK(hb1, bx1, by1);
            ACCPK(hb2, bx2, by2);
            ACCPK(hb3, bx3, by3);

            float wvA, ovA, wvB, ovB;
            RTREE(ax0,ay0,ax1,ay1,ax2,ay2,ax3,ay3, wvA, ovA);
            RTREE(bx0,by0,bx1,by1,bx2,by2,bx3,by3, wvB, ovB);
            EPILOG2(wvA, ovA, ppA, actA, cqA, jjqA);
            EPILOG2(wvB, ovB, ppB, actB, cqB, jjqB);
        } else {
            float wvA, ovA;
            RTREE(ax0,ay0,ax1,ay1,ax2,ay2,ax3,ay3, wvA, ovA);
            EPILOG2(wvA, ovA, ppA, actA, cqA, jjqA);
        }
        __syncthreads();
    }
#undef ACCPK
#undef QADDR
#undef RTREE
#undef EPILOG2

    // ---- depth-0 tail: projection GEMM P1 = h0 @ Wi[1] + b[1] -> g_P1 ----
    if (depth == 0) {
        const int c   = t >> 3;            // cell 0..63
        const int kb4 = (t & 7) * 4;
        unsigned long long acc[8];
#pragma unroll
        for (int i = 0; i < 8; i++) acc[i] = 0ull;
        const uint32_t uW  = (uint32_t)__cvta_generic_to_shared(STW) + kb4 * 4;
        const float* HrX = HXF + c * 68;
        const float* HrY = HYF + c * 68;
#pragma unroll 4
        for (int f = 0; f < Fc; f++) {
            unsigned long long hxd, hyd, w0, w1;
            float hx0 = HrX[f], hy0 = HrY[f];
            PACK2(hxd, hx0, hx0);
            PACK2(hyd, hy0, hy0);
            uint32_t wrow = uW + f * 512;
#pragma unroll
            for (int e4 = 0; e4 < 4; e4++) {
                LDSV2(w0, w1, wrow + e4 * 128);
                unsigned long long hd = (e4 < 2) ? hxd : hyd;
                FMA2(acc[2*e4],     hd, w0);
                FMA2(acc[2*e4 + 1], hd, w1);
            }
        }
        float* dst = &g_P1[b][ti][tj][0][0] + c * H2;
#pragma unroll
        for (int e4 = 0; e4 < 4; e4++) {
            int k = kb4 + e4 * 32;
            float4 bb = (k < Hc) ? *(const float4*)(bx + Hc + k)
                                 : *(const float4*)(by + k);   // by + Hc + (k-Hc)
            float p0, p1, p2, p3;
            UNPK2(p0, p1, acc[2*e4]);
            UNPK2(p2, p3, acc[2*e4 + 1]);
            float4 v = make_float4(p0 + bb.x, p1 + bb.y, p2 + bb.z, p3 + bb.w);
            *(float4*)(dst + k) = v;
        }
    }
}

// ---------------------------------------------------------------------------
static inline int diag_count(int d) {
    int lo2 = d - (TG - 1); if (lo2 < 0) lo2 = 0;
    int hi2 = (d < TG - 1) ? d : (TG - 1);
    return hi2 - lo2 + 1;
}

extern "C" void kernel_launch(void* const* d_in, const int* in_sizes, int n_in,
                              void* d_out, int out_size)
{
    const float* src = (const float*)d_in[0];
    const float* trg = (const float*)d_in[1];
    const float* Wix = (const float*)d_in[2];
    const float* Whx = (const float*)d_in[3];
    const float* bx  = (const float*)d_in[4];
    const float* Wiy = (const float*)d_in[5];
    const float* Why = (const float*)d_in[6];
    const float* by  = (const float*)d_in[7];
    const int*   slen = (const int*)d_in[8];
    const int*   tlen = (const int*)d_in[9];
    float* out = (float*)d_out;

    cudaFuncSetAttribute(wave_kernel,
                         cudaFuncAttributeMaxDynamicSharedMemorySize, SMEM_BYTES);

    proj0_kernel<<<Bc * (Sc + Tc), 64>>>(src, trg, Wix, Wiy);

    for (int ss = 0; ss <= NDIAG; ss++) {
        int nn0 = (ss < NDIAG) ? diag_count(ss) : 0;
        int nn1 = (ss >= 1) ? diag_count(ss - 1) : 0;
        int blocks = (nn0 + nn1) * Bc;
        if (blocks == 0) continue;
        wave_kernel<<<blocks, NTHREADS, SMEM_BYTES>>>(
            Whx, Why, bx, by, Wix, Wiy, slen, tlen, out, ss, nn0);
    }
}

// round 15
// speedup vs baseline: 1.7045x; 1.0025x over previous
#include <cuda_runtime.h>
#include <math.h>
#include <stdint.h>

#define Bc 8
#define Sc 96
#define Tc 96
#define Fc 64
#define Hc 64
#define H2 128
#define TILE 8
#define TG 12       // 96 / TILE
#define NDIAG 23    // 2*TG - 1
#define NTHREADS 512

// Unmasked recurrence state (scratch): halos read this (border cells only).
__device__ float g_hx[2][Bc][Sc][Tc][Hc];
__device__ float g_hy[2][Bc][Sc][Tc][Hc];
// Depth-0 input projections.
__device__ float g_px0[Bc][Sc][Hc];
__device__ float g_py0[Bc][Tc][Hc];
// Depth-1 per-cell input projections (bias folded), produced by d0 CTA tails.
__device__ float g_P1[Bc][TG][TG][64][H2];

__device__ __forceinline__ float ftanh(float x) {
    float e = __expf(-2.0f * fabsf(x));
    float r = __fdividef(1.0f - e, 1.0f + e);
    return copysignf(r, x);
}

// ---- packed f32x2 helpers (Blackwell) ----
#define FMA2(acc, a, b) asm("fma.rn.f32x2 %0, %1, %2, %0;" : "+l"(acc) : "l"(a), "l"(b))
#define MUL2(d, a, b)   asm("mul.rn.f32x2 %0, %1, %2;"     : "=l"(d)  : "l"(a), "l"(b))
#define ADD2(d, a, b)   asm("add.rn.f32x2 %0, %1, %2;"     : "=l"(d)  : "l"(a), "l"(b))
#define PACK2(d, lo, hi) asm("mov.b64 %0, {%1, %2};" : "=l"(d) : "f"(lo), "f"(hi))
#define UNPK2(lo, hi, s) asm("mov.b64 {%0, %1}, %2;" : "=f"(lo), "=f"(hi) : "l"(s))
#define LDSV2(a, b_, addr) \
    asm volatile("ld.shared.v2.b64 {%0, %1}, [%2];" : "=l"(a), "=l"(b_) : "r"(addr))

// ---------------------------------------------------------------------------
__global__ void proj0_kernel(const float* __restrict__ src,
                             const float* __restrict__ trg,
                             const float* __restrict__ Wix,
                             const float* __restrict__ Wiy)
{
    __shared__ float row[Fc];
    const int r = blockIdx.x;
    const int k = threadIdx.x;
    const float* W;
    const float* inrow;
    float* outp;
    if (r < Bc * Sc) {
        inrow = src + r * Fc;  W = Wix;  outp = &g_px0[0][0][0] + r * Hc;
    } else {
        int rr = r - Bc * Sc;
        inrow = trg + rr * Fc; W = Wiy;  outp = &g_py0[0][0][0] + rr * Hc;
    }
    row[k] = inrow[k];
    __syncthreads();
    float acc = 0.f;
#pragma unroll 8
    for (int f = 0; f < Fc; f++) acc += row[f] * W[f * Hc + k];
    outp[k] = acc;
}

// ---------------------------------------------------------------------------
// smem layout (floats):
//   [0     : 1024 )  d0: PXs[8][64], PYs[8][64]
//   [1024  : 9216 )  d0: STW [64][128] (Wi depth1)
//   [9216  : 13568)  d0: HXF [64][68]  full-tile hx outputs
//   [13568 : 17920)  d0: HYF [64][68]
//   [17920 : 18944)  HX [2][8][64]
//   [18944 : 19968)  HY [2][8][64]
//   [19968 : 20480)  HXtop [8][64]
//   [20480 : 20992)  HYleft [8][64]
//   [20992 : 21504)  pad (speculative-read guard)
#define SMEM_FLOATS 21504
#define SMEM_BYTES  (SMEM_FLOATS * 4)

__global__ void __launch_bounds__(NTHREADS, 1) wave_kernel(
    const float* __restrict__ Whx, const float* __restrict__ Why,
    const float* __restrict__ bx,  const float* __restrict__ by,
    const float* __restrict__ Wix, const float* __restrict__ Wiy,
    const int*   __restrict__ slen, const int* __restrict__ tlen,
    float* __restrict__ out, int s, int n0)
{
    extern __shared__ float smem[];
    float* PXs    = smem;             // d0
    float* PYs    = smem + 512;       // d0
    float* STW    = smem + 1024;      // d0
    float* HXF    = smem + 9216;      // d0
    float* HYF    = smem + 13568;     // d0
    float* HX     = smem + 17920;
    float* HY     = smem + 18944;
    float* HXtop  = smem + 19968;
    float* HYleft = smem + 20480;

    const uint32_t uHX     = (uint32_t)__cvta_generic_to_shared(HX);
    const uint32_t uHY     = (uint32_t)__cvta_generic_to_shared(HY);
    const uint32_t uHXtop  = (uint32_t)__cvta_generic_to_shared(HXtop);
    const uint32_t uHYleft = (uint32_t)__cvta_generic_to_shared(HYleft);

    const int t    = threadIdx.x;
    const int slot = blockIdx.x >> 3;
    const int b    = blockIdx.x & 7;

    int depth, diag, pos;
    if (slot < n0) { depth = 0; diag = s;     pos = slot; }
    else           { depth = 1; diag = s - 1; pos = slot - n0; }
    int lo = diag - (TG - 1); if (lo < 0) lo = 0;
    const int ti = lo + pos;
    const int tj = diag - ti;
    const int i0 = ti * TILE, j0 = tj * TILE;

    const float* bxd = bx + depth * Hc;
    const float* byd = by + depth * Hc;

    // ---- halos from neighbor tiles (border cells), zeros at grid border ----
    {
        int rr = t >> 6, k = t & 63;
        HXtop[t]  = (ti > 0) ? g_hx[depth][b][i0 - 1][j0 + rr][k] : 0.f;
        HYleft[t] = (tj > 0) ? g_hy[depth][b][i0 + rr][j0 - 1][k] : 0.f;
    }

    // ---- per-thread identity ----
    const int lane = t & 31;
    const int kq   = lane >> 2;                      // 0..7 : K-slice
    const int kh   = ((t >> 5) << 2) | (lane & 3);   // 0..63 : output pair
    const int k0   = kh * 2;
    const bool isx = (kh < 32);
    const int  kb  = isx ? k0 : (k0 - Hc);
    const int  hofsB = (kq & 3) * 64;                // byte offset of 16-float slice
    const int  rot   = (kq + (kq >> 2)) & 3;
    const int  cob0 = ((rot    ) & 3) * 16;
    const int  cob1 = ((rot + 1) & 3) * 16;
    const int  cob2 = ((rot + 2) & 3) * 16;
    const int  cob3 = ((rot + 3) & 3) * 16;

    // ---- register weights: packed pairs, rotated chunk order ----
    unsigned long long wxx[8], wyy[8];
    {
        const float* Wbase = isx ? (Whx + depth * H2 * Hc + k0)
                                 : (Why + depth * H2 * Hc + (k0 - Hc));
#pragma unroll
        for (int u = 0; u < 4; u++) {
            int cou = ((rot + u) & 3) * 4;
            int r = kq * 16 + cou;
            float2 wa = *(const float2*)(Wbase + (r + 0) * Hc);
            float2 wb = *(const float2*)(Wbase + (r + 1) * Hc);
            float2 wc = *(const float2*)(Wbase + (r + 2) * Hc);
            float2 wd = *(const float2*)(Wbase + (r + 3) * Hc);
            PACK2(wxx[2*u],   wa.x, wb.x);  PACK2(wyy[2*u],   wa.y, wb.y);
            PACK2(wxx[2*u+1], wc.x, wd.x);  PACK2(wyy[2*u+1], wc.y, wd.y);
        }
    }

    // ---- input projections ----
    if (depth == 0) {
        int rr = t >> 6, k = t & 63;
        PXs[t] = g_px0[b][i0 + rr][k] + bxd[k];
        PYs[t] = g_py0[b][j0 + rr][k] + byd[k];
        // stage depth-1 Wi for the projection tail
        for (int idx = t; idx < 64 * H2; idx += NTHREADS) {
            int f = idx >> 7, k2 = idx & 127;
            STW[idx] = (k2 < Hc) ? Wix[Fc * Hc + f * Hc + k2]
                                 : Wiy[Fc * Hc + f * Hc + (k2 - Hc)];
        }
    }
    // depth-1: P read directly from g_P1 (L2-hot), no smem copy
    __syncthreads();

    // ---- epilogue bases ----
    const int slb = slen[b], tlb = tlen[b];
    float* gB = (isx ? &g_hx[depth][b][0][0][0] : &g_hy[depth][b][0][0][0]) + kb;
    float* oB = out + ((size_t)((isx ? 0 : 2) + depth) * Bc + b)
                      * ((size_t)Sc * Tc * Hc) + kb;
    float* hB = (isx ? HX : HY) + kb;
    float* hF = (isx ? HXF : HYF) + kb;
    const float* pB = (depth == 0) ? ((isx ? PXs : PYs) + kb)
                                   : (&g_P1[b][ti][tj][0][0] + k0);
    const int dPc = (depth == 0) ? (isx ? 64 : -64) : (7 * H2);
    const bool evenkq = ((kq & 1) == 0);
    const int  qown   = kq >> 1;

#define ACCPK(HSADDR, AX, AY) do {                                            \
        unsigned long long _h01,_h23,_ax,_ay,_bx2,_by2;                       \
        LDSV2(_h01,_h23,(HSADDR) + cob0);                                     \
        MUL2(_ax,_h01,wxx[0]);  MUL2(_ay,_h01,wyy[0]);                        \
        FMA2(_ax,_h23,wxx[1]);  FMA2(_ay,_h23,wyy[1]);                        \
        LDSV2(_h01,_h23,(HSADDR) + cob1);                                     \
        MUL2(_bx2,_h01,wxx[2]); MUL2(_by2,_h01,wyy[2]);                       \
        FMA2(_bx2,_h23,wxx[3]); FMA2(_by2,_h23,wyy[3]);                       \
        LDSV2(_h01,_h23,(HSADDR) + cob2);                                     \
        FMA2(_ax,_h01,wxx[4]);  FMA2(_ay,_h01,wyy[4]);                        \
        FMA2(_ax,_h23,wxx[5]);  FMA2(_ay,_h23,wyy[5]);                        \
        LDSV2(_h01,_h23,(HSADDR) + cob3);                                     \
        FMA2(_bx2,_h01,wxx[6]); FMA2(_by2,_h01,wyy[6]);                       \
        FMA2(_bx2,_h23,wxx[7]); FMA2(_by2,_h23,wyy[7]);                       \
        ADD2(_ax,_ax,_bx2); ADD2(_ay,_ay,_by2);                               \
        float _l,_h;                                                          \
        UNPK2(_l,_h,_ax); AX = _l + _h;                                       \
        UNPK2(_l,_h,_ay); AY = _l + _h;                                       \
    } while (0)

// compute the 4 h-slice smem addresses for a quad starting at cell CB
#define QADDR(CB, H0, H1, H2_, H3) do {                                       \
        _Pragma("unroll")                                                     \
        for (int q = 0; q < 4; q++) {                                         \
            int cq = (CB) + q, jjq = dd - cq;                                 \
            uint32_t pa = (cq > 0)  ? uHX + hprvB + (cq - 1) * 256            \
                                    : uHXtop + jjq * 256;                     \
            uint32_t pb = (jjq > 0) ? uHY + hprvB + cq * 256                  \
                                    : uHYleft + cq * 256;                     \
            uint32_t hq = ((kq < 4) ? pa : pb) + hofsB;                       \
            if (q == 0) H0 = hq; else if (q == 1) H1 = hq;                    \
            else if (q == 2) H2_ = hq; else H3 = hq;                          \
        }                                                                     \
    } while (0)

// reduce-scatter across the 8 kq groups: group g owns (cell CB+(g>>1), comp g&1)
#define RTREE(AX0,AY0,AX1,AY1,AX2,AY2,AX3,AY3, WV, OV) do {                   \
        const unsigned FULL = 0xffffffffu;                                    \
        bool hi2 = (kq & 4);                                                  \
        float sv, rv, t0, t1, t2, t3, v0, v1;                                 \
        sv = hi2 ? AX0 : AX2; rv = __shfl_xor_sync(FULL, sv, 16);             \
        t0 = (hi2 ? AX2 : AX0) + rv;                                          \
        sv = hi2 ? AY0 : AY2; rv = __shfl_xor_sync(FULL, sv, 16);             \
        t1 = (hi2 ? AY2 : AY0) + rv;                                          \
        sv = hi2 ? AX1 : AX3; rv = __shfl_xor_sync(FULL, sv, 16);             \
        t2 = (hi2 ? AX3 : AX1) + rv;                                          \
        sv = hi2 ? AY1 : AY3; rv = __shfl_xor_sync(FULL, sv, 16);             \
        t3 = (hi2 ? AY3 : AY1) + rv;                                          \
        bool b1 = (kq & 2);                                                   \
        sv = b1 ? t0 : t2; rv = __shfl_xor_sync(FULL, sv, 8);                 \
        v0 = (b1 ? t2 : t0) + rv;                                             \
        sv = b1 ? t1 : t3; rv = __shfl_xor_sync(FULL, sv, 8);                 \
        v1 = (b1 ? t3 : t1) + rv;                                             \
        bool b0 = (kq & 1);                                                   \
        sv = b0 ? v0 : v1; rv = __shfl_xor_sync(FULL, sv, 4);                 \
        WV = (b0 ? v1 : v0) + rv;                                             \
        OV = __shfl_xor_sync(FULL, WV, 4);                                    \
    } while (0)

#define EPILOG2(WV, OV, PP, ACT, CQ, JJQ) do {                                \
        float rx = ftanh((PP).x + (WV));                                      \
        float ry = ftanh((PP).y + (OV));                                      \
        if ((ACT) && evenkq) {                                                \
            float2 v = make_float2(rx, ry);                                   \
            *(float2*)(hB + hcur + (CQ) * 64) = v;                            \
            int go = ((i0 + (CQ)) * Tc + (j0 + (JJQ))) * Hc;                  \
            if (depth == 0)                                                   \
                *(float2*)(hF + ((CQ) * TILE + (JJQ)) * 68) = v;              \
            if ((CQ) == TILE - 1 || (JJQ) == TILE - 1)                        \
                *(float2*)(gB + go) = v;                                      \
            bool m = ((i0 + (CQ)) < slb) && ((j0 + (JJQ)) < tlb);             \
            float2 mv = m ? v : make_float2(0.f, 0.f);                        \
            *(float2*)(oB + go) = mv;                                         \
        }                                                                     \
    } while (0)

    // ---- intra-tile wavefront: ONE straight-line region per diagonal ----
    for (int dd = 0; dd < 2 * TILE - 1; dd++) {
        int iilo = dd - (TILE - 1); if (iilo < 0) iilo = 0;
        int iihi = (dd < TILE - 1) ? dd : (TILE - 1);
        int cur = dd & 1, prv = cur ^ 1;
        int hcur = cur * 512, hprvB = prv * 2048;

        const int  cbA  = iilo;
        const bool twoQ = (iihi - iilo) >= 4;

        // quad A: ownership + prefetch pp
        int  cqA  = cbA + qown, jjqA = dd - cqA;
        bool actA = (cqA <= iihi);
        int  pofA_base = (depth == 0) ? ((isx ? cbA : (dd - cbA)) * 64)
                                      : ((cbA * TILE + (dd - cbA)) * H2);
        int  pofA = actA ? (pofA_base + qown * dPc) : 0;
        float2 ppA = *(const float2*)(pB + pofA);

        // quad B: ownership + prefetch pp (act-guarded -> safe when !twoQ)
        const int cbB = cbA + 4;
        int  cqB  = cbB + qown, jjqB = dd - cqB;
        bool actB = (cqB <= iihi);
        int  pofB_base = (depth == 0) ? ((isx ? cbB : (dd - cbB)) * 64)
                                      : ((cbB * TILE + (dd - cbB)) * H2);
        int  pofB = actB ? (pofB_base + qown * dPc) : 0;
        float2 ppB = *(const float2*)(pB + pofB);

        uint32_t ha0, ha1, ha2, ha3;
        QADDR(cbA, ha0, ha1, ha2, ha3);

        float ax0,ay0,ax1,ay1,ax2,ay2,ax3,ay3;
        ACCPK(ha0, ax0, ay0);
        ACCPK(ha1, ax1, ay1);
        ACCPK(ha2, ax2, ay2);
        ACCPK(ha3, ax3, ay3);

        if (twoQ) {
            uint32_t hb0, hb1, hb2, hb3;
            QADDR(cbB, hb0, hb1, hb2, hb3);
            float bx0,by0,bx1,by1,bx2,by2,bx3,by3;
            ACCPK(hb0, bx0, by0);
            ACCPK(hb1, bx1, by1);
            ACCPK(hb2, bx2, by2);
            ACCPK(hb3, bx3, by3);

            float wvA, ovA, wvB, ovB;
            RTREE(ax0,ay0,ax1,ay1,ax2,ay2,ax3,ay3, wvA, ovA);
            RTREE(bx0,by0,bx1,by1,bx2,by2,bx3,by3, wvB, ovB);
            EPILOG2(wvA, ovA, ppA, actA, cqA, jjqA);
            EPILOG2(wvB, ovB, ppB, actB, cqB, jjqB);
        } else {
            float wvA, ovA;
            RTREE(ax0,ay0,ax1,ay1,ax2,ay2,ax3,ay3, wvA, ovA);
            EPILOG2(wvA, ovA, ppA, actA, cqA, jjqA);
        }
        __syncthreads();
    }
#undef ACCPK
#undef QADDR
#undef RTREE
#undef EPILOG2

    // ---- depth-0 tail: projection GEMM P1 = h0 @ Wi[1] + b[1] -> g_P1 ----
    if (depth == 0) {
        const int c   = t >> 3;            // cell 0..63
        const int kb4 = (t & 7) * 4;
        unsigned long long acc[8];
#pragma unroll
        for (int i = 0; i < 8; i++) acc[i] = 0ull;
        const uint32_t uW  = (uint32_t)__cvta_generic_to_shared(STW) + kb4 * 4;
        const float* HrX = HXF + c * 68;
        const float* HrY = HYF + c * 68;
#pragma unroll 4
        for (int f = 0; f < Fc; f++) {
            unsigned long long hxd, hyd, w0, w1;
            float hx0 = HrX[f], hy0 = HrY[f];
            PACK2(hxd, hx0, hx0);
            PACK2(hyd, hy0, hy0);
            uint32_t wrow = uW + f * 512;
#pragma unroll
            for (int e4 = 0; e4 < 4; e4++) {
                LDSV2(w0, w1, wrow + e4 * 128);
                unsigned long long hd = (e4 < 2) ? hxd : hyd;
                FMA2(acc[2*e4],     hd, w0);
                FMA2(acc[2*e4 + 1], hd, w1);
            }
        }
        float* dst = &g_P1[b][ti][tj][0][0] + c * H2;
#pragma unroll
        for (int e4 = 0; e4 < 4; e4++) {
            int k = kb4 + e4 * 32;
            float4 bb = (k < Hc) ? *(const float4*)(bx + Hc + k)
                                 : *(const float4*)(by + k);   // by + Hc + (k-Hc)
            float p0, p1, p2, p3;
            UNPK2(p0, p1, acc[2*e4]);
            UNPK2(p2, p3, acc[2*e4 + 1]);
            float4 v = make_float4(p0 + bb.x, p1 + bb.y, p2 + bb.z, p3 + bb.w);
            *(float4*)(dst + k) = v;
        }
    }
}

// ---------------------------------------------------------------------------
static inline int diag_count(int d) {
    int lo2 = d - (TG - 1); if (lo2 < 0) lo2 = 0;
    int hi2 = (d < TG - 1) ? d : (TG - 1);
    return hi2 - lo2 + 1;
}

extern "C" void kernel_launch(void* const* d_in, const int* in_sizes, int n_in,
                              void* d_out, int out_size)
{
    const float* src = (const float*)d_in[0];
    const float* trg = (const float*)d_in[1];
    const float* Wix = (const float*)d_in[2];
    const float* Whx = (const float*)d_in[3];
    const float* bx  = (const float*)d_in[4];
    const float* Wiy = (const float*)d_in[5];
    const float* Why = (const float*)d_in[6];
    const float* by  = (const float*)d_in[7];
    const int*   slen = (const int*)d_in[8];
    const int*   tlen = (const int*)d_in[9];
    float* out = (float*)d_out;

    cudaFuncSetAttribute(wave_kernel,
                         cudaFuncAttributeMaxDynamicSharedMemorySize, SMEM_BYTES);

    proj0_kernel<<<Bc * (Sc + Tc), 64>>>(src, trg, Wix, Wiy);

    for (int ss = 0; ss <= NDIAG; ss++) {
        int nn0 = (ss < NDIAG) ? diag_count(ss) : 0;
        int nn1 = (ss >= 1) ? diag_count(ss - 1) : 0;
        int blocks = (nn0 + nn1) * Bc;
        if (blocks == 0) continue;
        wave_kernel<<<blocks, NTHREADS, SMEM_BYTES>>>(
            Whx, Why, bx, by, Wix, Wiy, slen, tlen, out, ss, nn0);
    }
}